// round 6
// baseline (speedup 1.0000x reference)
#include <cuda_runtime.h>
#include <math.h>

#define Bsz   4096
#define Lh    64
#define Dh    16
#define Hh    128
#define ROWS  32
#define THREADS 256
#define CTAS  128
#define HEAD_IN 144
#define OUTD  60
#define SQ    (Hh*Hh)
#define NPAIR (Hh/2)

typedef unsigned long long ull;

#define FMA2(acc, a, b) \
    asm("fma.rn.f32x2 %0, %1, %2, %3;" : "=l"(acc) : "l"(a), "l"(b), "l"(acc))
#define PACK2(d, lo, hi) \
    asm("mov.b64 %0, {%1, %2};" : "=l"(d) : "f"(lo), "f"(hi))

__device__ __forceinline__ float2 unpack2(ull v) {
    float2 r;
    asm("mov.b64 {%0, %1}, %2;" : "=f"(r.x), "=f"(r.y) : "l"(v));
    return r;
}

// pre-packed weights, k-contiguous for coalesced LDG.128:
// g_wg[l][pair][0][k]=(wi,wo)  [1][k]=(wc,ui)  [2][k]=(uo,uc)
__device__ ulonglong2 g_wg[2][NPAIR][3][Hh];
__device__ ull        g_wd[2][NPAIR][Hh];

__global__ void pack_kernel(const float* __restrict__ Wx,
                            const float* __restrict__ Uh,
                            const float* __restrict__ Wd)
{
    int idx = blockIdx.x * blockDim.x + threadIdx.x;
    if (idx >= 2 * NPAIR * Hh) return;
    int k = idx & (Hh - 1);
    int p = (idx >> 7) & (NPAIR - 1);
    int l = idx >> 13;
    int j0 = 2 * p, j1 = j0 + 1;

    const float* wx = Wx + (size_t)l * 4 * SQ;
    const float* uh = Uh + (size_t)l * 4 * SQ;

    ull wi, wo, wc, ui, uo, uc, wd;
    PACK2(wi, wx[1*SQ + j0*Hh + k], wx[1*SQ + j1*Hh + k]);
    PACK2(wo, wx[2*SQ + j0*Hh + k], wx[2*SQ + j1*Hh + k]);
    PACK2(wc, wx[3*SQ + j0*Hh + k], wx[3*SQ + j1*Hh + k]);
    PACK2(ui, uh[1*SQ + j0*Hh + k], uh[1*SQ + j1*Hh + k]);
    PACK2(uo, uh[2*SQ + j0*Hh + k], uh[2*SQ + j1*Hh + k]);
    PACK2(uc, uh[3*SQ + j0*Hh + k], uh[3*SQ + j1*Hh + k]);
    const float* wdm = Wd + (size_t)l * SQ;
    PACK2(wd, wdm[j0*Hh + k], wdm[j1*Hh + k]);

    ulonglong2 v;
    v.x = wi; v.y = wo; g_wg[l][p][0][k] = v;
    v.x = wc; v.y = ui; g_wg[l][p][1][k] = v;
    v.x = uo; v.y = uc; g_wg[l][p][2][k] = v;
    g_wd[l][p][k] = wd;
}

struct SM {
    float h[2][ROWS][Hh];
    float c[2][ROWS][Hh];
    float xin[ROWS][Hh];
    float ht[ROWS][Hh];
    float sv[ROWS][Hh];
    float wp[Dh][Hh];
    float histb[ROWS][Dh];
    float msk[ROWS];
    float dec[ROWS];
    int   last[ROWS];
};

__device__ __forceinline__ float tanh_f(float x) {
    float e = __expf(2.0f * x);
    return 1.0f - __fdividef(2.0f, e + 1.0f);
}
__device__ __forceinline__ float sig_f(float x) {
    return __fdividef(1.0f, 1.0f + __expf(-x));
}

__device__ __forceinline__ float fixv(float x) {
    if (!(x == x)) return 0.0f;
    if (x > 1e38f) return 1e4f;
    if (x < -1e38f) return -1e4f;
    return x;
}

__global__ void __launch_bounds__(THREADS, 1)
tlstm_kernel(const float* __restrict__ history, const float* __restrict__ hmask,
             const float* __restrict__ Wp,  const float* __restrict__ bp,
             const float* __restrict__ bx,  const float* __restrict__ bd,
             const float* __restrict__ Wt,  const float* __restrict__ bt,
             const float* __restrict__ ln_g, const float* __restrict__ ln_b,
             const float* __restrict__ W1,  const float* __restrict__ b1,
             const float* __restrict__ W2,  const float* __restrict__ b2,
             float* __restrict__ out)
{
    extern __shared__ char smraw[];
    SM* sm = reinterpret_cast<SM*>(smraw);

    const int tid  = threadIdx.x;
    const int b0   = blockIdx.x * ROWS;
    const int w    = tid >> 5;
    const int lane = tid & 31;
    const int wk   = w & 3;           // 4 warps along k
    const int wr   = w >> 2;          // 2 row groups
    const int half = lane >> 4;
    const int kk   = lane & 15;
    const int k0   = wk * 16 + kk;    // first output channel
    const int k1   = k0 + 64;         // second output channel
    const int rb   = wr * 16 + half * 8;

    for (int i = tid; i < 2 * ROWS * Hh; i += THREADS) {
        (&sm->h[0][0][0])[i] = 0.0f;
        (&sm->c[0][0][0])[i] = 0.0f;
    }
    for (int i = tid; i < Dh * Hh; i += THREADS)
        (&sm->wp[0][0])[i] = Wp[i];
    if (tid < ROWS) {
        const float* mp = hmask + (size_t)(b0 + tid) * Lh;
        float s = 0.0f;
        for (int t = 0; t < Lh; t++) s += mp[t];
        s = fminf(fmaxf(s, 1.0f), (float)Lh);
        sm->last[tid] = (int)s - 1;
    }
    __syncthreads();

    // per-thread constants for both k channels
    float bpk[2], bxi[2][2], bxo[2][2], bxc[2][2], bdl[2][2], wtl[2][2], btl[2][2];
    {
        int ks[2] = {k0, k1};
        #pragma unroll
        for (int q = 0; q < 2; q++) {
            int k = ks[q];
            bpk[q] = bp[k];
            bxi[0][q] = bx[1*Hh + k]; bxo[0][q] = bx[2*Hh + k]; bxc[0][q] = bx[3*Hh + k];
            bxi[1][q] = bx[5*Hh + k]; bxo[1][q] = bx[6*Hh + k]; bxc[1][q] = bx[7*Hh + k];
            bdl[0][q] = bd[k];        bdl[1][q] = bd[Hh + k];
            wtl[0][q] = Wt[k];        wtl[1][q] = Wt[Hh + k];
            btl[0][q] = bt[k];        btl[1][q] = bt[Hh + k];
        }
    }

    // ================= time loop =================
    for (int t = 0; t < Lh; t++) {
        for (int i = tid; i < ROWS * Dh; i += THREADS) {
            int r = i >> 4, d = i & 15;
            sm->histb[r][d] = history[((size_t)(b0 + r) * Lh + t) * Dh + d];
        }
        if (tid < ROWS)
            sm->msk[tid] = hmask[(size_t)(b0 + tid) * Lh + t];
        __syncthreads();

        if (tid < ROWS) {
            float dd = fmaxf(sm->histb[tid][5], 0.0f);
            sm->dec[tid] = 1.0f / logf(2.718281828459045f + dd);
        }
        // x_t = hist @ Wp + bp  (both k channels)
        {
            float a0[8], a1[8];
            #pragma unroll
            for (int rr = 0; rr < 8; rr++) { a0[rr] = bpk[0]; a1[rr] = bpk[1]; }
            #pragma unroll
            for (int d = 0; d < Dh; d++) {
                float w0 = sm->wp[d][k0];
                float w1 = sm->wp[d][k1];
                #pragma unroll
                for (int rr = 0; rr < 8; rr++) {
                    float hv = sm->histb[rb + rr][d];
                    a0[rr] += hv * w0;
                    a1[rr] += hv * w1;
                }
            }
            #pragma unroll
            for (int rr = 0; rr < 8; rr++) {
                sm->xin[rb + rr][k0] = a0[rr];
                sm->xin[rb + rr][k1] = a1[rr];
            }
        }
        __syncthreads();

        #pragma unroll
        for (int l = 0; l < 2; l++) {
            const float* inp  = (l == 0) ? &sm->xin[0][0] : &sm->h[0][0][0];
            float*       hcur = &sm->h[l][0][0];

            // packed accumulators: 3 gates x 2 k x 8 rows
            ull zi2[16], zo2[16], zc2[16];
            #pragma unroll
            for (int q = 0; q < 2; q++) {
                #pragma unroll
                for (int rr = 0; rr < 8; rr++) {
                    PACK2(zi2[q*8+rr], bxi[l][q], 0.0f);
                    PACK2(zo2[q*8+rr], bxo[l][q], 0.0f);
                    PACK2(zc2[q*8+rr], bxc[l][q], 0.0f);
                }
            }

            const ulonglong2* __restrict__ pw = &g_wg[l][0][0][0];
            #pragma unroll 2
            for (int p = 0; p < NPAIR; p++) {
                ulonglong2 wa0 = pw[k0];          // (wi,wo) k0
                ulonglong2 wb0 = pw[Hh + k0];     // (wc,ui) k0
                ulonglong2 wc0 = pw[2*Hh + k0];   // (uo,uc) k0
                ulonglong2 wa1 = pw[k1];
                ulonglong2 wb1 = pw[Hh + k1];
                ulonglong2 wc1 = pw[2*Hh + k1];
                const int j = 2 * p;
                #pragma unroll
                for (int rr = 0; rr < 8; rr++) {
                    const int r = rb + rr;
                    ull xu = *reinterpret_cast<const ull*>(inp  + r*Hh + j);
                    ull hu = *reinterpret_cast<const ull*>(hcur + r*Hh + j);
                    FMA2(zi2[rr],   xu, wa0.x);
                    FMA2(zo2[rr],   xu, wa0.y);
                    FMA2(zc2[rr],   xu, wb0.x);
                    FMA2(zi2[rr],   hu, wb0.y);
                    FMA2(zo2[rr],   hu, wc0.x);
                    FMA2(zc2[rr],   hu, wc0.y);
                    FMA2(zi2[8+rr], xu, wa1.x);
                    FMA2(zo2[8+rr], xu, wa1.y);
                    FMA2(zc2[8+rr], xu, wb1.x);
                    FMA2(zi2[8+rr], hu, wb1.y);
                    FMA2(zo2[8+rr], hu, wc1.x);
                    FMA2(zc2[8+rr], hu, wc1.y);
                }
                pw += 3 * Hh;
            }

            float ot[16], htl[16];
            #pragma unroll
            for (int q = 0; q < 2; q++) {
                const int k = q ? k1 : k0;
                #pragma unroll
                for (int rr = 0; rr < 8; rr++) {
                    float2 a = unpack2(zi2[q*8+rr]);
                    float2 b = unpack2(zo2[q*8+rr]);
                    float2 c = unpack2(zc2[q*8+rr]);
                    float it = sig_f(a.x + a.y);
                    ot[q*8+rr]  = sig_f(b.x + b.y);
                    htl[q*8+rr] = tanh_f(c.x + c.y) + it;
                    sm->ht[rb + rr][k] = htl[q*8+rr];
                }
            }
            __syncthreads();

            // h_short = tanh(h_tilde @ Wd + bd)
            const ull* __restrict__ pd = &g_wd[l][0][0];
            ull hs2[16];
            #pragma unroll
            for (int q = 0; q < 2; q++)
                #pragma unroll
                for (int rr = 0; rr < 8; rr++)
                    PACK2(hs2[q*8+rr], bdl[l][q], 0.0f);
            #pragma unroll 4
            for (int p = 0; p < NPAIR; p++) {
                ull wd0 = pd[k0];
                ull wd1 = pd[k1];
                const int j = 2 * p;
                #pragma unroll
                for (int rr = 0; rr < 8; rr++) {
                    ull t2 = *reinterpret_cast<const ull*>(&sm->ht[rb + rr][j]);
                    FMA2(hs2[rr],   t2, wd0);
                    FMA2(hs2[8+rr], t2, wd1);
                }
                pd += Hh;
            }

            #pragma unroll
            for (int q = 0; q < 2; q++) {
                const int k = q ? k1 : k0;
                #pragma unroll
                for (int rr = 0; rr < 8; rr++) {
                    const int r = rb + rr;
                    float2 av   = unpack2(hs2[q*8+rr]);
                    float hs    = tanh_f(av.x + av.y);
                    float dt    = sig_f(sm->dec[r] * wtl[l][q] + btl[l][q]);
                    float hstar = (htl[q*8+rr] - hs) + hs * dt;
                    float cold  = sm->c[l][r][k];
                    float cn    = tanh_f(hstar + ot[q*8+rr] * cold);
                    float hn    = ot[q*8+rr] * tanh_f(cn);
                    float m     = sm->msk[r];
                    float hv    = m * hn + (1.0f - m) * hcur[r*Hh + k];
                    float cv    = m * cn + (1.0f - m) * cold;
                    sm->c[l][r][k] = cv;
                    hcur[r*Hh + k] = hv;
                    if (l == 1 && t == sm->last[r])
                        sm->sv[r][k] = m * hv;
                }
            }
            __syncthreads();
        }
    }

    // ================= forecast head =================
    for (int i = tid; i < ROWS * Dh; i += THREADS) {
        int r = i >> 4, d = i & 15;
        sm->histb[r][d] = history[((size_t)(b0 + r) * Lh + sm->last[r]) * Dh + d];
    }
    __syncthreads();

    const unsigned FULL = 0xffffffffu;
    #pragma unroll
    for (int rr = 0; rr < 4; rr++) {
        const int r = w * 4 + rr;

        float s = 0.0f, s2 = 0.0f;
        for (int i = lane; i < HEAD_IN; i += 32) {
            float v = (i < 16) ? sm->histb[r][i] : sm->sv[r][i - 16];
            s += v; s2 += v * v;
        }
        #pragma unroll
        for (int off = 16; off; off >>= 1) {
            s  += __shfl_xor_sync(FULL, s,  off);
            s2 += __shfl_xor_sync(FULL, s2, off);
        }
        float mean = s / (float)HEAD_IN;
        float var  = s2 / (float)HEAD_IN - mean * mean;
        float rstd = rsqrtf(var + 1e-5f);

        const int j0 = lane * 4;
        float4 acc = *reinterpret_cast<const float4*>(b1 + j0);
        for (int i = 0; i < HEAD_IN; i++) {
            float v  = (i < 16) ? sm->histb[r][i] : sm->sv[r][i - 16];
            float sn = (v - mean) * rstd * ln_g[i] + ln_b[i];
            float4 w4 = *reinterpret_cast<const float4*>(W1 + i * Hh + j0);
            acc.x += sn * w4.x; acc.y += sn * w4.y;
            acc.z += sn * w4.z; acc.w += sn * w4.w;
        }
        float y[4] = { fmaxf(acc.x, 0.0f), fmaxf(acc.y, 0.0f),
                       fmaxf(acc.z, 0.0f), fmaxf(acc.w, 0.0f) };

        const int o0 = lane, o1 = lane + 32;
        float a0 = b2[o0];
        float a1 = (o1 < OUTD) ? b2[o1] : 0.0f;
        #pragma unroll
        for (int q = 0; q < 4; q++) {
            float yq = y[q];
            #pragma unroll 8
            for (int src = 0; src < 32; src++) {
                float v = __shfl_sync(FULL, yq, src);
                int   j = src * 4 + q;
                a0 += v * W2[j * OUTD + o0];
                if (o1 < OUTD) a1 += v * W2[j * OUTD + o1];
            }
        }
        size_t ob = (size_t)(b0 + r) * OUTD;
        out[ob + o0] = fixv(a0);
        if (o1 < OUTD) out[ob + o1] = fixv(a1);
    }
}

extern "C" void kernel_launch(void* const* d_in, const int* in_sizes, int n_in,
                              void* d_out, int out_size)
{
    const float* history = (const float*)d_in[0];
    const float* hmask   = (const float*)d_in[1];
    const float* Wp      = (const float*)d_in[2];
    const float* bp      = (const float*)d_in[3];
    const float* Wx      = (const float*)d_in[4];
    const float* bx      = (const float*)d_in[5];
    const float* Uh      = (const float*)d_in[6];
    const float* Wd      = (const float*)d_in[7];
    const float* bd      = (const float*)d_in[8];
    const float* Wt      = (const float*)d_in[9];
    const float* bt      = (const float*)d_in[10];
    const float* ln_g    = (const float*)d_in[11];
    const float* ln_b    = (const float*)d_in[12];
    const float* W1      = (const float*)d_in[13];
    const float* b1      = (const float*)d_in[14];
    const float* W2      = (const float*)d_in[15];
    const float* b2      = (const float*)d_in[16];

    pack_kernel<<<(2 * NPAIR * Hh + 255) / 256, 256>>>(Wx, Uh, Wd);

    cudaFuncSetAttribute(tlstm_kernel,
                         cudaFuncAttributeMaxDynamicSharedMemorySize,
                         (int)sizeof(SM));
    tlstm_kernel<<<CTAS, THREADS, sizeof(SM)>>>(
        history, hmask, Wp, bp, bx, bd, Wt, bt,
        ln_g, ln_b, W1, b1, W2, b2, (float*)d_out);
}